// round 15
// baseline (speedup 1.0000x reference)
#include <cuda_runtime.h>
#include <math.h>

#define SD     16
#define IDIM   64
#define ODIM   64
#define NBATCH 32
#define SEQLEN 8192
#define LCH    32
#define NCH    (SEQLEN/LCH)
#define NSUP   16
#define NSC    (NCH/NSUP)
#define DTVAL  1.0f
#define FULLMASK 0xffffffffu

__device__ __align__(16) float g_Ad[SD*SD];
__device__ __align__(16) float g_Bd[SD*IDIM];
__device__ __align__(16) float g_Apow[LCH*SD*SD];
__device__ __align__(16) float g_ALpow[17*SD*SD];
__device__ __align__(16) float g_H[NBATCH*SEQLEN*SD];
__device__ __align__(16) float g_Pfx[NBATCH*NSC*17*SD];
__device__ __align__(16) float g_Hsup[NBATCH*NSC*SD];

// ---------------- K0: discretization + power tables ----------------
__global__ void k0_setup(const float* __restrict__ ll, const float* __restrict__ p,
                         const float* __restrict__ q,  const float* __restrict__ B,
                         const float* __restrict__ P) {
    __shared__ float core[SD*SD], tmp[SD*SD], Ac[SD*SD];
    __shared__ float aug[SD][96];
    __shared__ float fvec[SD];
    __shared__ float prow[96];
    int t = threadIdx.x;

    if (t < SD*SD) {
        int i = t >> 4, j = t & 15;
        float v = p[i] * q[j];
        if (i == j) v -= expf(ll[i]);
        core[t] = v;
    }
    __syncthreads();
    if (t < SD*SD) {
        int i = t >> 4, j = t & 15;
        float s = 0.f;
        for (int k = 0; k < SD; k++) s += P[i*SD+k] * core[k*SD+j];
        tmp[t] = s;
    }
    __syncthreads();
    if (t < SD*SD) {
        int i = t >> 4, j = t & 15;
        float s = 0.f;
        for (int k = 0; k < SD; k++) s += tmp[i*SD+k] * P[j*SD+k];
        Ac[t] = s;
    }
    __syncthreads();
    for (int f = t; f < SD*96; f += 256) {
        int r = f / 96, c = f % 96;
        float v;
        if (c < 16)      v = (r == c      ? 1.f : 0.f) - 0.5f*DTVAL*Ac[r*SD+c];
        else if (c < 32) v = (r == (c-16) ? 1.f : 0.f) + 0.5f*DTVAL*Ac[r*SD+(c-16)];
        else             v = DTVAL * B[r*IDIM + (c-32)];
        aug[r][c] = v;
    }
    __syncthreads();
    for (int col = 0; col < SD; col++) {
        if (t < 96) prow[t] = aug[col][t];
        if (t < SD) fvec[t] = aug[t][col];
        __syncthreads();
        float ipv = 1.f / prow[col];
        for (int f = t; f < SD*96; f += 256) {
            int r = f / 96, c = f % 96;
            if (r == col) aug[r][c] = prow[c] * ipv;
            else          aug[r][c] = fmaf(-fvec[r]*ipv, prow[c], aug[r][c]);
        }
        __syncthreads();
    }
    if (t < SD*SD) { int r = t >> 4, c = t & 15; float v = aug[r][16+c]; g_Ad[t] = v; g_Apow[t] = v; }
    for (int f = t; f < SD*IDIM; f += 256) { int r = f / IDIM, c = f % IDIM; g_Bd[f] = aug[r][32+c]; }
    __syncthreads();
    for (int m = 1; m <= LCH/2; m <<= 1) {
        for (int f = t; f < m*256; f += 256) {
            int i = f >> 8, e = f & 255, r = e >> 4, c2 = e & 15;
            const float* L = g_Apow + i*256 + r*16;
            const float* R = g_Apow + (m-1)*256;
            float s = 0.f;
#pragma unroll
            for (int k = 0; k < 16; k++) s = fmaf(L[k], R[k*16 + c2], s);
            g_Apow[(m+i)*256 + e] = s;
        }
        __syncthreads();
    }
    if (t < 256) {
        int r = t >> 4, c = t & 15;
        g_ALpow[t] = (r == c) ? 1.f : 0.f;
        g_ALpow[256 + t] = g_Apow[(LCH-1)*256 + t];
    }
    __syncthreads();
    for (int m = 1; m <= 8; m <<= 1) {
        for (int f = t; f < m*256; f += 256) {
            int i = (f >> 8) + 1, e = f & 255, r = e >> 4, c2 = e & 15;
            const float* L = g_ALpow + i*256 + r*16;
            const float* R = g_ALpow + m*256;
            float s = 0.f;
#pragma unroll
            for (int k = 0; k < 16; k++) s = fmaf(L[k], R[k*16 + c2], s);
            g_ALpow[(m+i)*256 + e] = s;
        }
        __syncthreads();
    }
}

// ---------------- kBxS: u = x @ Bd^T + in-smem local scan ----------------
#define XSTR 66
#define USTR 20
__global__ void __launch_bounds__(256) kbxs(const float* __restrict__ x) {
    __shared__ __align__(16) float Xs[128*XSTR];
    __shared__ float Bs[16*66];
    __shared__ float As[16*17];
    int tid = threadIdx.x;
    size_t row0 = (size_t)blockIdx.x * 128;

    for (int i = tid; i < SD*IDIM; i += 256) {
        int nn = i >> 6, kk = i & 63;
        Bs[nn*66 + kk] = g_Bd[i];
    }
    if (tid < SD*SD) As[(tid >> 4)*17 + (tid & 15)] = g_Ad[tid];
#pragma unroll
    for (int i = 0; i < 16; i++) {
        int f = tid + 256*i;
        int r = f >> 5, qq = f & 31;
        float2 v = *(const float2*)(x + (row0 + r)*64 + qq*2);
        *(float2*)&Xs[r*XSTR + qq*2] = v;
    }
    __syncthreads();

    unsigned long long acc[4][4];
    int tr = tid >> 2, tc = tid & 3;
    if (tid < 128) {
#pragma unroll
        for (int m = 0; m < 4; m++)
#pragma unroll
            for (int c = 0; c < 4; c++) acc[m][c] = 0ull;
        const float* xa = Xs + (tr*4)*XSTR;
#pragma unroll
        for (int kp = 0; kp < 32; kp++) {
            unsigned long long a2[4], b2[4];
#pragma unroll
            for (int m = 0; m < 4; m++)
                a2[m] = *(const unsigned long long*)(xa + m*XSTR + 2*kp);
#pragma unroll
            for (int c = 0; c < 4; c++)
                b2[c] = *(const unsigned long long*)(Bs + (tc + 4*c)*66 + 2*kp);
#pragma unroll
            for (int m = 0; m < 4; m++)
#pragma unroll
                for (int c = 0; c < 4; c++)
                    asm("fma.rn.f32x2 %0, %1, %2, %0;"
                        : "+l"(acc[m][c]) : "l"(a2[m]), "l"(b2[c]));
        }
    }
    __syncthreads();
    float* Us = Xs;
    if (tid < 128) {
#pragma unroll
        for (int m = 0; m < 4; m++)
#pragma unroll
            for (int c = 0; c < 4; c++) {
                float lo, hi;
                asm("mov.b64 {%0,%1}, %2;" : "=f"(lo), "=f"(hi) : "l"(acc[m][c]));
                Us[(tr*4 + m)*USTR + tc + 4*c] = lo + hi;
            }
    }
    __syncthreads();

    if (tid < 64) {
        int hw = tid >> 4, n = tid & 15;
        float Ar[16];
#pragma unroll
        for (int k = 0; k < 16; k++) Ar[k] = As[n*17 + k];
        float* u = Us + hw*32*USTR + n;
        float h = 0.f;
        float uc = u[0];
#pragma unroll
        for (int i = 0; i < LCH; i++) {
            float un = (i < LCH-1) ? u[(i+1)*USTR] : 0.f;
            float acc0 = uc, acc1 = 0.f, acc2 = 0.f, acc3 = 0.f;
#pragma unroll
            for (int m = 0; m < 16; m += 4) {
                acc0 = fmaf(Ar[m],   __shfl_sync(FULLMASK, h, m,   16), acc0);
                acc1 = fmaf(Ar[m+1], __shfl_sync(FULLMASK, h, m+1, 16), acc1);
                acc2 = fmaf(Ar[m+2], __shfl_sync(FULLMASK, h, m+2, 16), acc2);
                acc3 = fmaf(Ar[m+3], __shfl_sync(FULLMASK, h, m+3, 16), acc3);
            }
            h = (acc0 + acc1) + (acc2 + acc3);
            u[i*USTR] = h;
            uc = un;
        }
    }
    __syncthreads();

#pragma unroll
    for (int i = 0; i < 2; i++) {
        int f = tid + 256*i;
        int r = f >> 2, qq = f & 3;
        float4 v = *(const float4*)&Us[r*USTR + qq*4];
        *(float4*)(g_H + row0*SD + (size_t)f*4) = v;
    }
}

// ---------------- k2ab: superchunk prefixes + cross-superchunk scan ----------------
__global__ void __launch_bounds__(256) k2ab() {
    int tid = threadIdx.x;
    int b = blockIdx.x;
    int n = tid & 15;
    {
        int g = b*NSC + (tid >> 4);
        float Ar[16];
#pragma unroll
        for (int k = 0; k < 16; k++) Ar[k] = g_ALpow[256 + n*16 + k];
        float Pv = 0.f;
#pragma unroll
        for (int j = 0; j < NSUP; j++) {
            g_Pfx[(g*17 + j)*16 + n] = Pv;
            int c = g*NSUP + j;
            float s = g_H[((size_t)c*LCH + (LCH-1))*SD + n];
            float acc0 = s, acc1 = 0.f, acc2 = 0.f, acc3 = 0.f;
#pragma unroll
            for (int m = 0; m < 16; m += 4) {
                acc0 = fmaf(Ar[m],   __shfl_sync(FULLMASK, Pv, m,   16), acc0);
                acc1 = fmaf(Ar[m+1], __shfl_sync(FULLMASK, Pv, m+1, 16), acc1);
                acc2 = fmaf(Ar[m+2], __shfl_sync(FULLMASK, Pv, m+2, 16), acc2);
                acc3 = fmaf(Ar[m+3], __shfl_sync(FULLMASK, Pv, m+3, 16), acc3);
            }
            Pv = (acc0 + acc1) + (acc2 + acc3);
        }
        g_Pfx[(g*17 + 16)*16 + n] = Pv;
    }
    __syncthreads();
    if (tid < 16) {
        float Ar[16];
#pragma unroll
        for (int k = 0; k < 16; k++) Ar[k] = g_ALpow[16*256 + n*16 + k];
        float H = 0.f;
#pragma unroll
        for (int s = 0; s < NSC; s++) {
            int g = b*NSC + s;
            g_Hsup[g*16 + n] = H;
            float P16 = g_Pfx[(g*17 + 16)*16 + n];
            float acc0 = P16, acc1 = 0.f, acc2 = 0.f, acc3 = 0.f;
#pragma unroll
            for (int m = 0; m < 16; m += 4) {
                acc0 = fmaf(Ar[m],   __shfl_sync(FULLMASK, H, m,   16), acc0);
                acc1 = fmaf(Ar[m+1], __shfl_sync(FULLMASK, H, m+1, 16), acc1);
                acc2 = fmaf(Ar[m+2], __shfl_sync(FULLMASK, H, m+2, 16), acc2);
                acc3 = fmaf(Ar[m+3], __shfl_sync(FULLMASK, H, m+3, 16), acc3);
            }
            H = (acc0 + acc1) + (acc2 + acc3);
        }
    }
}

// ---------------- K3h: Y = [X|H] @ [D|C]^T, 512 thr, warp tile 16x32, LDS.128 ----------------
#define ZSTR 44
#define WSTR 84
#define APAD 17
__global__ void __launch_bounds__(512, 1) k3h(const float* __restrict__ x,
                                              const float* __restrict__ C,
                                              const float* __restrict__ D,
                                              float* __restrict__ y) {
    __shared__ __align__(16) float Zs[128*ZSTR];     // 22.0 KB
    __shared__ __align__(16) float Ws[64*WSTR];      // 21.0 KB
    __shared__ float sA4[4*16*APAD];
    __shared__ float hpv[4*16];
    int tid = threadIdx.x;
    size_t row0 = (size_t)blockIdx.x * 128;
    int wid = tid >> 5;
    int wrow = (wid & 7) * 16, wcol = (wid >> 3) * 32;
    int lr = (tid >> 3) & 3, lc = tid & 7;

    // W = [D|C]
#pragma unroll
    for (int i = 0; i < 4; i++) {
        int f = tid + 512*i;
        int o = f >> 5, k0 = (f & 31) << 1;
        float2 v = *(const float2*)(D + o*64 + k0);
        *(float2*)&Ws[o*WSTR + k0] = v;
    }
    {
        int o = tid >> 3, k0 = (tid & 7) << 1;
        float2 v = *(const float2*)(C + o*16 + k0);
        *(float2*)&Ws[o*WSTR + 64 + k0] = v;
    }
    // A^1..A^4
#pragma unroll
    for (int i = 0; i < 2; i++) {
        int f = tid + 512*i;
        int jl = f >> 8, e = f & 255;
        sA4[jl*(16*APAD) + (e >> 4)*APAD + (e & 15)] = g_Apow[f];
    }
    // hprev per chunk
    if (tid < 64) {
        int cl = tid >> 4, n = tid & 15;
        int cg = blockIdx.x*4 + cl;
        int gsup = cg >> 4, js = cg & 15;
        float s = g_Pfx[((size_t)gsup*17 + js)*16 + n];
        const float* alr = g_ALpow + js*256 + n*16;
        const float* hs = g_Hsup + gsup*16;
#pragma unroll
        for (int k = 0; k < 16; k++) s = fmaf(alr[k], hs[k], s);
        hpv[cl*16 + n] = s;
    }

    unsigned long long acc[4][4];
#pragma unroll
    for (int m = 0; m < 4; m++)
#pragma unroll
        for (int c = 0; c < 4; c++) acc[m][c] = 0ull;

    const float* za0 = Zs + (wrow + lr*4)*ZSTR;
    const float* wb0 = Ws + (wcol + lc)*WSTR;

    // ---- phase 1 staging: x k0..39 ----
#pragma unroll
    for (int i = 0; i < 3; i++) {
        int f = tid + 512*i;
        if (f < 1280) {
            int r = f / 10, qq = f % 10;
            float4 v = *(const float4*)(x + (row0 + r)*64 + qq*4);
            *(float4*)&Zs[r*ZSTR + qq*4] = v;
        }
    }
    __syncthreads();
#pragma unroll
    for (int kq = 0; kq < 10; kq++) {
        ulonglong2 a4[4], b4[4];
#pragma unroll
        for (int m = 0; m < 4; m++)
            a4[m] = *(const ulonglong2*)(za0 + m*ZSTR + 4*kq);
#pragma unroll
        for (int c = 0; c < 4; c++)
            b4[c] = *(const ulonglong2*)(wb0 + (8*c)*WSTR + 4*kq);
#pragma unroll
        for (int m = 0; m < 4; m++)
#pragma unroll
            for (int c = 0; c < 4; c++) {
                asm("fma.rn.f32x2 %0, %1, %2, %0;" : "+l"(acc[m][c]) : "l"(a4[m].x), "l"(b4[c].x));
                asm("fma.rn.f32x2 %0, %1, %2, %0;" : "+l"(acc[m][c]) : "l"(a4[m].y), "l"(b4[c].y));
            }
    }
    __syncthreads();
    // ---- phase 2 staging: x k40..63 -> cols 0..23, l -> cols 24..39 ----
#pragma unroll
    for (int i = 0; i < 2; i++) {
        int f = tid + 512*i;
        if (f < 768) {
            int r = f / 6, qq = f % 6;
            float4 v = *(const float4*)(x + (row0 + r)*64 + 40 + qq*4);
            *(float4*)&Zs[r*ZSTR + qq*4] = v;
        }
    }
    {
        int r = tid >> 2, qq = tid & 3;
        float4 v = *(const float4*)(g_H + (row0 + r)*16 + qq*4);
        *(float4*)&Zs[r*ZSTR + 24 + qq*4] = v;
    }
    __syncthreads();
    // ---- correction chains (16 half-warps in tid<256) ----
    if (tid < 256) {
        int hw = tid >> 4, cl = hw >> 2, mph = hw & 3, n = tid & 15;
        const float* Am = sA4 + mph*(16*APAD) + n*APAD;
        const float* hp = hpv + cl*16;
        float w = 0.f;
#pragma unroll
        for (int k = 0; k < 16; k++) w = fmaf(Am[k], hp[k], w);
        float A4r[16];
#pragma unroll
        for (int k = 0; k < 16; k++) A4r[k] = sA4[3*(16*APAD) + n*APAD + k];
#pragma unroll
        for (int s = 0; s < 8; s++) {
            int j = mph + 4*s;
            Zs[(cl*32 + j)*ZSTR + 24 + n] += w;
            if (s < 7) {
                float a0 = 0.f, a1 = 0.f, a2 = 0.f, a3 = 0.f;
#pragma unroll
                for (int m = 0; m < 16; m += 4) {
                    a0 = fmaf(A4r[m],   __shfl_sync(FULLMASK, w, m,   16), a0);
                    a1 = fmaf(A4r[m+1], __shfl_sync(FULLMASK, w, m+1, 16), a1);
                    a2 = fmaf(A4r[m+2], __shfl_sync(FULLMASK, w, m+2, 16), a2);
                    a3 = fmaf(A4r[m+3], __shfl_sync(FULLMASK, w, m+3, 16), a3);
                }
                w = (a0 + a1) + (a2 + a3);
            }
        }
    }
    __syncthreads();
    // ---- phase 2 compute (k 40..79) ----
#pragma unroll
    for (int kq = 0; kq < 10; kq++) {
        ulonglong2 a4[4], b4[4];
#pragma unroll
        for (int m = 0; m < 4; m++)
            a4[m] = *(const ulonglong2*)(za0 + m*ZSTR + 4*kq);
#pragma unroll
        for (int c = 0; c < 4; c++)
            b4[c] = *(const ulonglong2*)(wb0 + (8*c)*WSTR + 40 + 4*kq);
#pragma unroll
        for (int m = 0; m < 4; m++)
#pragma unroll
            for (int c = 0; c < 4; c++) {
                asm("fma.rn.f32x2 %0, %1, %2, %0;" : "+l"(acc[m][c]) : "l"(a4[m].x), "l"(b4[c].x));
                asm("fma.rn.f32x2 %0, %1, %2, %0;" : "+l"(acc[m][c]) : "l"(a4[m].y), "l"(b4[c].y));
            }
    }

#pragma unroll
    for (int m = 0; m < 4; m++) {
        size_t row = row0 + wrow + lr*4 + m;
#pragma unroll
        for (int c = 0; c < 4; c++) {
            float lo, hi;
            asm("mov.b64 {%0,%1}, %2;" : "=f"(lo), "=f"(hi) : "l"(acc[m][c]));
            y[row*64 + wcol + lc + 8*c] = lo + hi;
        }
    }
}

extern "C" void kernel_launch(void* const* d_in, const int* in_sizes, int n_in,
                              void* d_out, int out_size) {
    const float* x  = (const float*)d_in[0];
    const float* ll = (const float*)d_in[1];
    const float* p  = (const float*)d_in[2];
    const float* q  = (const float*)d_in[3];
    const float* B  = (const float*)d_in[4];
    const float* C  = (const float*)d_in[5];
    const float* D  = (const float*)d_in[6];
    const float* P  = (const float*)d_in[7];
    float* y = (float*)d_out;

    k0_setup<<<1, 256>>>(ll, p, q, B, P);
    kbxs<<<(NBATCH*SEQLEN)/128, 256>>>(x);
    k2ab<<<NBATCH, 256>>>();
    k3h<<<(NBATCH*SEQLEN)/128, 512>>>(x, C, D, y);   // profiled slot (4th)
}

// round 16
// speedup vs baseline: 1.1397x; 1.1397x over previous
#include <cuda_runtime.h>
#include <math.h>

#define SD     16
#define IDIM   64
#define ODIM   64
#define NBATCH 32
#define SEQLEN 8192
#define LCH    32
#define NCH    (SEQLEN/LCH)
#define NSUP   16
#define NSC    (NCH/NSUP)
#define DTVAL  1.0f
#define FULLMASK 0xffffffffu

__device__ __align__(16) float g_Ad[SD*SD];
__device__ __align__(16) float g_Bd[SD*IDIM];
__device__ __align__(16) float g_Apow[LCH*SD*SD];
__device__ __align__(16) float g_ALpow[17*SD*SD];
__device__ __align__(16) float g_H[NBATCH*SEQLEN*SD];
__device__ __align__(16) float g_Pfx[NBATCH*NSC*17*SD];
__device__ __align__(16) float g_Hsup[NBATCH*NSC*SD];

// ---------------- K0: discretization + power tables ----------------
__global__ void k0_setup(const float* __restrict__ ll, const float* __restrict__ p,
                         const float* __restrict__ q,  const float* __restrict__ B,
                         const float* __restrict__ P) {
    __shared__ float core[SD*SD], tmp[SD*SD], Ac[SD*SD];
    __shared__ float aug[SD][96];
    __shared__ float fvec[SD];
    __shared__ float prow[96];
    int t = threadIdx.x;

    if (t < SD*SD) {
        int i = t >> 4, j = t & 15;
        float v = p[i] * q[j];
        if (i == j) v -= expf(ll[i]);
        core[t] = v;
    }
    __syncthreads();
    if (t < SD*SD) {
        int i = t >> 4, j = t & 15;
        float s = 0.f;
        for (int k = 0; k < SD; k++) s += P[i*SD+k] * core[k*SD+j];
        tmp[t] = s;
    }
    __syncthreads();
    if (t < SD*SD) {
        int i = t >> 4, j = t & 15;
        float s = 0.f;
        for (int k = 0; k < SD; k++) s += tmp[i*SD+k] * P[j*SD+k];
        Ac[t] = s;
    }
    __syncthreads();
    for (int f = t; f < SD*96; f += 256) {
        int r = f / 96, c = f % 96;
        float v;
        if (c < 16)      v = (r == c      ? 1.f : 0.f) - 0.5f*DTVAL*Ac[r*SD+c];
        else if (c < 32) v = (r == (c-16) ? 1.f : 0.f) + 0.5f*DTVAL*Ac[r*SD+(c-16)];
        else             v = DTVAL * B[r*IDIM + (c-32)];
        aug[r][c] = v;
    }
    __syncthreads();
    for (int col = 0; col < SD; col++) {
        if (t < 96) prow[t] = aug[col][t];
        if (t < SD) fvec[t] = aug[t][col];
        __syncthreads();
        float ipv = 1.f / prow[col];
        for (int f = t; f < SD*96; f += 256) {
            int r = f / 96, c = f % 96;
            if (r == col) aug[r][c] = prow[c] * ipv;
            else          aug[r][c] = fmaf(-fvec[r]*ipv, prow[c], aug[r][c]);
        }
        __syncthreads();
    }
    if (t < SD*SD) { int r = t >> 4, c = t & 15; float v = aug[r][16+c]; g_Ad[t] = v; g_Apow[t] = v; }
    for (int f = t; f < SD*IDIM; f += 256) { int r = f / IDIM, c = f % IDIM; g_Bd[f] = aug[r][32+c]; }
    __syncthreads();
    for (int m = 1; m <= LCH/2; m <<= 1) {
        for (int f = t; f < m*256; f += 256) {
            int i = f >> 8, e = f & 255, r = e >> 4, c2 = e & 15;
            const float* L = g_Apow + i*256 + r*16;
            const float* R = g_Apow + (m-1)*256;
            float s = 0.f;
#pragma unroll
            for (int k = 0; k < 16; k++) s = fmaf(L[k], R[k*16 + c2], s);
            g_Apow[(m+i)*256 + e] = s;
        }
        __syncthreads();
    }
    if (t < 256) {
        int r = t >> 4, c = t & 15;
        g_ALpow[t] = (r == c) ? 1.f : 0.f;
        g_ALpow[256 + t] = g_Apow[(LCH-1)*256 + t];
    }
    __syncthreads();
    for (int m = 1; m <= 8; m <<= 1) {
        for (int f = t; f < m*256; f += 256) {
            int i = (f >> 8) + 1, e = f & 255, r = e >> 4, c2 = e & 15;
            const float* L = g_ALpow + i*256 + r*16;
            const float* R = g_ALpow + m*256;
            float s = 0.f;
#pragma unroll
            for (int k = 0; k < 16; k++) s = fmaf(L[k], R[k*16 + c2], s);
            g_ALpow[(m+i)*256 + e] = s;
        }
        __syncthreads();
    }
}

// ---------------- kBxS: u = x @ Bd^T + in-smem local scan ----------------
#define XSTR 66
#define USTR 20
__global__ void __launch_bounds__(256) kbxs(const float* __restrict__ x) {
    __shared__ __align__(16) float Xs[128*XSTR];
    __shared__ float Bs[16*66];
    __shared__ float As[16*17];
    int tid = threadIdx.x;
    size_t row0 = (size_t)blockIdx.x * 128;

    for (int i = tid; i < SD*IDIM; i += 256) {
        int nn = i >> 6, kk = i & 63;
        Bs[nn*66 + kk] = g_Bd[i];
    }
    if (tid < SD*SD) As[(tid >> 4)*17 + (tid & 15)] = g_Ad[tid];
#pragma unroll
    for (int i = 0; i < 16; i++) {
        int f = tid + 256*i;
        int r = f >> 5, qq = f & 31;
        float2 v = *(const float2*)(x + (row0 + r)*64 + qq*2);
        *(float2*)&Xs[r*XSTR + qq*2] = v;
    }
    __syncthreads();

    unsigned long long acc[4][4];
    int tr = tid >> 2, tc = tid & 3;
    if (tid < 128) {
#pragma unroll
        for (int m = 0; m < 4; m++)
#pragma unroll
            for (int c = 0; c < 4; c++) acc[m][c] = 0ull;
        const float* xa = Xs + (tr*4)*XSTR;
#pragma unroll
        for (int kp = 0; kp < 32; kp++) {
            unsigned long long a2[4], b2[4];
#pragma unroll
            for (int m = 0; m < 4; m++)
                a2[m] = *(const unsigned long long*)(xa + m*XSTR + 2*kp);
#pragma unroll
            for (int c = 0; c < 4; c++)
                b2[c] = *(const unsigned long long*)(Bs + (tc + 4*c)*66 + 2*kp);
#pragma unroll
            for (int m = 0; m < 4; m++)
#pragma unroll
                for (int c = 0; c < 4; c++)
                    asm("fma.rn.f32x2 %0, %1, %2, %0;"
                        : "+l"(acc[m][c]) : "l"(a2[m]), "l"(b2[c]));
        }
    }
    __syncthreads();
    float* Us = Xs;
    if (tid < 128) {
#pragma unroll
        for (int m = 0; m < 4; m++)
#pragma unroll
            for (int c = 0; c < 4; c++) {
                float lo, hi;
                asm("mov.b64 {%0,%1}, %2;" : "=f"(lo), "=f"(hi) : "l"(acc[m][c]));
                Us[(tr*4 + m)*USTR + tc + 4*c] = lo + hi;
            }
    }
    __syncthreads();

    if (tid < 64) {
        int hw = tid >> 4, n = tid & 15;
        float Ar[16];
#pragma unroll
        for (int k = 0; k < 16; k++) Ar[k] = As[n*17 + k];
        float* u = Us + hw*32*USTR + n;
        float h = 0.f;
        float uc = u[0];
#pragma unroll
        for (int i = 0; i < LCH; i++) {
            float un = (i < LCH-1) ? u[(i+1)*USTR] : 0.f;
            float acc0 = uc, acc1 = 0.f, acc2 = 0.f, acc3 = 0.f;
#pragma unroll
            for (int m = 0; m < 16; m += 4) {
                acc0 = fmaf(Ar[m],   __shfl_sync(FULLMASK, h, m,   16), acc0);
                acc1 = fmaf(Ar[m+1], __shfl_sync(FULLMASK, h, m+1, 16), acc1);
                acc2 = fmaf(Ar[m+2], __shfl_sync(FULLMASK, h, m+2, 16), acc2);
                acc3 = fmaf(Ar[m+3], __shfl_sync(FULLMASK, h, m+3, 16), acc3);
            }
            h = (acc0 + acc1) + (acc2 + acc3);
            u[i*USTR] = h;
            uc = un;
        }
    }
    __syncthreads();

#pragma unroll
    for (int i = 0; i < 2; i++) {
        int f = tid + 256*i;
        int r = f >> 2, qq = f & 3;
        float4 v = *(const float4*)&Us[r*USTR + qq*4];
        *(float4*)(g_H + row0*SD + (size_t)f*4) = v;
    }
}

// ---------------- k2ab: superchunk prefixes + cross-superchunk scan ----------------
__global__ void __launch_bounds__(256) k2ab() {
    int tid = threadIdx.x;
    int b = blockIdx.x;
    int n = tid & 15;
    {
        int g = b*NSC + (tid >> 4);
        float Ar[16];
#pragma unroll
        for (int k = 0; k < 16; k++) Ar[k] = g_ALpow[256 + n*16 + k];
        float Pv = 0.f;
#pragma unroll
        for (int j = 0; j < NSUP; j++) {
            g_Pfx[(g*17 + j)*16 + n] = Pv;
            int c = g*NSUP + j;
            float s = g_H[((size_t)c*LCH + (LCH-1))*SD + n];
            float acc0 = s, acc1 = 0.f, acc2 = 0.f, acc3 = 0.f;
#pragma unroll
            for (int m = 0; m < 16; m += 4) {
                acc0 = fmaf(Ar[m],   __shfl_sync(FULLMASK, Pv, m,   16), acc0);
                acc1 = fmaf(Ar[m+1], __shfl_sync(FULLMASK, Pv, m+1, 16), acc1);
                acc2 = fmaf(Ar[m+2], __shfl_sync(FULLMASK, Pv, m+2, 16), acc2);
                acc3 = fmaf(Ar[m+3], __shfl_sync(FULLMASK, Pv, m+3, 16), acc3);
            }
            Pv = (acc0 + acc1) + (acc2 + acc3);
        }
        g_Pfx[(g*17 + 16)*16 + n] = Pv;
    }
    __syncthreads();
    if (tid < 16) {
        float Ar[16];
#pragma unroll
        for (int k = 0; k < 16; k++) Ar[k] = g_ALpow[16*256 + n*16 + k];
        float H = 0.f;
#pragma unroll
        for (int s = 0; s < NSC; s++) {
            int g = b*NSC + s;
            g_Hsup[g*16 + n] = H;
            float P16 = g_Pfx[(g*17 + 16)*16 + n];
            float acc0 = P16, acc1 = 0.f, acc2 = 0.f, acc3 = 0.f;
#pragma unroll
            for (int m = 0; m < 16; m += 4) {
                acc0 = fmaf(Ar[m],   __shfl_sync(FULLMASK, H, m,   16), acc0);
                acc1 = fmaf(Ar[m+1], __shfl_sync(FULLMASK, H, m+1, 16), acc1);
                acc2 = fmaf(Ar[m+2], __shfl_sync(FULLMASK, H, m+2, 16), acc2);
                acc3 = fmaf(Ar[m+3], __shfl_sync(FULLMASK, H, m+3, 16), acc3);
            }
            H = (acc0 + acc1) + (acc2 + acc3);
        }
    }
}

// ---------------- K3i: 128 thr, 8x8 thread tile, col-packed f32x2, k-major W ----------------
#define ZSTR 42
#define WKS  72
#define APAD2 17
__global__ void __launch_bounds__(128, 4) k3i(const float* __restrict__ x,
                                              const float* __restrict__ C,
                                              const float* __restrict__ D,
                                              float* __restrict__ y) {
    __shared__ float Zs[128*ZSTR];           // 21.5 KB, row-major [row][kpanel(40)]
    __shared__ float Wk[80*WKS];             // 23.0 KB, k-major [k][col]
    __shared__ float sA2[2*16*APAD2];        // A^1, A^2
    __shared__ float hpv[4*16];
    int tid = threadIdx.x;
    size_t row0 = (size_t)blockIdx.x * 128;
    int wid = tid >> 5;
    int wrow = wid * 32;
    int lr = (tid >> 3) & 3, lc = tid & 7;

    // Wk fill: D (coalesced read, transposed store)
#pragma unroll
    for (int i = 0; i < 32; i++) {
        int f = tid + 128*i;                 // 4096 = 64o x 64k
        int o = f >> 6, k = f & 63;
        Wk[k*WKS + o] = D[f];
    }
#pragma unroll
    for (int i = 0; i < 8; i++) {
        int f = tid + 128*i;                 // 1024 = 64o x 16k
        int o = f >> 4, kk = f & 15;
        Wk[(64 + kk)*WKS + o] = C[f];
    }
    // A^1, A^2
#pragma unroll
    for (int i = 0; i < 4; i++) {
        int f = tid + 128*i;                 // 512
        int jl = f >> 8, e = f & 255;
        sA2[jl*(16*APAD2) + (e >> 4)*APAD2 + (e & 15)] = g_Apow[f];
    }
    // hprev per chunk
    if (tid < 64) {
        int cl = tid >> 4, n = tid & 15;
        int cg = blockIdx.x*4 + cl;
        int gsup = cg >> 4, js = cg & 15;
        float s = g_Pfx[((size_t)gsup*17 + js)*16 + n];
        const float* alr = g_ALpow + js*256 + n*16;
        const float* hs = g_Hsup + gsup*16;
#pragma unroll
        for (int k = 0; k < 16; k++) s = fmaf(alr[k], hs[k], s);
        hpv[cl*16 + n] = s;
    }
    // phase-1 staging: x k0..39 (float2; ZSTR=42 keeps 8B alignment)
#pragma unroll
    for (int i = 0; i < 20; i++) {
        int f = tid + 128*i;                 // 2560 float2
        int r = f / 20, q = f % 20;
        float2 v = *(const float2*)(x + (row0 + r)*64 + 2*q);
        *(float2*)&Zs[r*ZSTR + 2*q] = v;
    }

    unsigned long long acc[8][4];            // col-packed: (col, col+1)
#pragma unroll
    for (int m = 0; m < 8; m++)
#pragma unroll
        for (int c = 0; c < 4; c++) acc[m][c] = 0ull;

    const float* za0 = Zs + (wrow + lr*8)*ZSTR;
    __syncthreads();

    // ---- phase 1 compute: k 0..39 ----
#pragma unroll 4
    for (int k = 0; k < 40; k++) {
        const float* wr = Wk + k*WKS + 2*lc;
        unsigned long long b2[4];
        b2[0] = *(const unsigned long long*)(wr);
        b2[1] = *(const unsigned long long*)(wr + 16);
        b2[2] = *(const unsigned long long*)(wr + 32);
        b2[3] = *(const unsigned long long*)(wr + 48);
#pragma unroll
        for (int m = 0; m < 8; m++) {
            float a = za0[m*ZSTR + k];
            unsigned long long a2;
            asm("mov.b64 %0, {%1, %1};" : "=l"(a2) : "f"(a));
#pragma unroll
            for (int c = 0; c < 4; c++)
                asm("fma.rn.f32x2 %0, %1, %2, %0;"
                    : "+l"(acc[m][c]) : "l"(a2), "l"(b2[c]));
        }
    }
    __syncthreads();
    // ---- phase 2 staging: x k40..63 -> cols 0..23, l -> cols 24..39 ----
#pragma unroll
    for (int i = 0; i < 12; i++) {
        int f = tid + 128*i;                 // 1536 float2
        int r = f / 12, q = f % 12;
        float2 v = *(const float2*)(x + (row0 + r)*64 + 40 + 2*q);
        *(float2*)&Zs[r*ZSTR + 2*q] = v;
    }
#pragma unroll
    for (int i = 0; i < 8; i++) {
        int f = tid + 128*i;                 // 1024 float2
        int r = f >> 3, q = f & 7;
        float2 v = *(const float2*)(g_H + (row0 + r)*16 + 2*q);
        *(float2*)&Zs[r*ZSTR + 24 + 2*q] = v;
    }
    __syncthreads();
    // ---- correction chains: 8 half-warps, A^2 steps, 16 iterations ----
    {
        int hw = tid >> 4, cl = hw >> 1, mph = hw & 1, n = tid & 15;
        const float* Am = sA2 + mph*(16*APAD2) + n*APAD2;   // A^{mph+1} row n
        const float* hp = hpv + cl*16;
        float w = 0.f;
#pragma unroll
        for (int k = 0; k < 16; k++) w = fmaf(Am[k], hp[k], w);
        float A2r[16];
#pragma unroll
        for (int k = 0; k < 16; k++) A2r[k] = sA2[1*(16*APAD2) + n*APAD2 + k];
#pragma unroll
        for (int s = 0; s < 16; s++) {
            int j = mph + 2*s;
            Zs[(cl*32 + j)*ZSTR + 24 + n] += w;
            if (s < 15) {
                float a0 = 0.f, a1 = 0.f, a2 = 0.f, a3 = 0.f;
#pragma unroll
                for (int m = 0; m < 16; m += 4) {
                    a0 = fmaf(A2r[m],   __shfl_sync(FULLMASK, w, m,   16), a0);
                    a1 = fmaf(A2r[m+1], __shfl_sync(FULLMASK, w, m+1, 16), a1);
                    a2 = fmaf(A2r[m+2], __shfl_sync(FULLMASK, w, m+2, 16), a2);
                    a3 = fmaf(A2r[m+3], __shfl_sync(FULLMASK, w, m+3, 16), a3);
                }
                w = (a0 + a1) + (a2 + a3);
            }
        }
    }
    __syncthreads();
    // ---- phase 2 compute: k 40..79 ----
#pragma unroll 4
    for (int k = 0; k < 40; k++) {
        const float* wr = Wk + (40 + k)*WKS + 2*lc;
        unsigned long long b2[4];
        b2[0] = *(const unsigned long long*)(wr);
        b2[1] = *(const unsigned long long*)(wr + 16);
        b2[2] = *(const unsigned long long*)(wr + 32);
        b2[3] = *(const unsigned long long*)(wr + 48);
#pragma unroll
        for (int m = 0; m < 8; m++) {
            float a = za0[m*ZSTR + k];
            unsigned long long a2;
            asm("mov.b64 %0, {%1, %1};" : "=l"(a2) : "f"(a));
#pragma unroll
            for (int c = 0; c < 4; c++)
                asm("fma.rn.f32x2 %0, %1, %2, %0;"
                    : "+l"(acc[m][c]) : "l"(a2), "l"(b2[c]));
        }
    }

    // ---- store: each u64 = two adjacent cols -> float2 ----
#pragma unroll
    for (int m = 0; m < 8; m++) {
        size_t row = row0 + wrow + lr*8 + m;
#pragma unroll
        for (int c = 0; c < 4; c++) {
            float lo, hi;
            asm("mov.b64 {%0,%1}, %2;" : "=f"(lo), "=f"(hi) : "l"(acc[m][c]));
            *(float2*)&y[row*64 + 2*lc + 16*c] = make_float2(lo, hi);
        }
    }
}

extern "C" void kernel_launch(void* const* d_in, const int* in_sizes, int n_in,
                              void* d_out, int out_size) {
    const float* x  = (const float*)d_in[0];
    const float* ll = (const float*)d_in[1];
    const float* p  = (const float*)d_in[2];
    const float* q  = (const float*)d_in[3];
    const float* B  = (const float*)d_in[4];
    const float* C  = (const float*)d_in[5];
    const float* D  = (const float*)d_in[6];
    const float* P  = (const float*)d_in[7];
    float* y = (float*)d_out;

    k0_setup<<<1, 256>>>(ll, p, q, B, P);
    kbxs<<<(NBATCH*SEQLEN)/128, 256>>>(x);
    k2ab<<<NBATCH, 256>>>();
    k3i<<<(NBATCH*SEQLEN)/128, 128>>>(x, C, D, y);   // profiled slot (4th)
}

// round 17
// speedup vs baseline: 1.2193x; 1.0699x over previous
#include <cuda_runtime.h>
#include <math.h>

#define SD     16
#define IDIM   64
#define ODIM   64
#define NBATCH 32
#define SEQLEN 8192
#define LCH    32
#define NCH    (SEQLEN/LCH)
#define NSUP   16
#define NSC    (NCH/NSUP)
#define DTVAL  1.0f
#define FULLMASK 0xffffffffu

__device__ __align__(16) float g_Ad[SD*SD];
__device__ __align__(16) float g_Bd[SD*IDIM];
__device__ __align__(16) float g_Apow[LCH*SD*SD];
__device__ __align__(16) float g_ALpow[17*SD*SD];
__device__ __align__(16) float g_H[NBATCH*SEQLEN*SD];
__device__ __align__(16) float g_Pfx[NBATCH*NSC*17*SD];
__device__ __align__(16) float g_Hsup[NBATCH*NSC*SD];

// ---------------- K0: discretization + power tables ----------------
__global__ void k0_setup(const float* __restrict__ ll, const float* __restrict__ p,
                         const float* __restrict__ q,  const float* __restrict__ B,
                         const float* __restrict__ P) {
    __shared__ float core[SD*SD], tmp[SD*SD], Ac[SD*SD];
    __shared__ float aug[SD][96];
    __shared__ float fvec[SD];
    __shared__ float prow[96];
    int t = threadIdx.x;

    if (t < SD*SD) {
        int i = t >> 4, j = t & 15;
        float v = p[i] * q[j];
        if (i == j) v -= expf(ll[i]);
        core[t] = v;
    }
    __syncthreads();
    if (t < SD*SD) {
        int i = t >> 4, j = t & 15;
        float s = 0.f;
        for (int k = 0; k < SD; k++) s += P[i*SD+k] * core[k*SD+j];
        tmp[t] = s;
    }
    __syncthreads();
    if (t < SD*SD) {
        int i = t >> 4, j = t & 15;
        float s = 0.f;
        for (int k = 0; k < SD; k++) s += tmp[i*SD+k] * P[j*SD+k];
        Ac[t] = s;
    }
    __syncthreads();
    for (int f = t; f < SD*96; f += 256) {
        int r = f / 96, c = f % 96;
        float v;
        if (c < 16)      v = (r == c      ? 1.f : 0.f) - 0.5f*DTVAL*Ac[r*SD+c];
        else if (c < 32) v = (r == (c-16) ? 1.f : 0.f) + 0.5f*DTVAL*Ac[r*SD+(c-16)];
        else             v = DTVAL * B[r*IDIM + (c-32)];
        aug[r][c] = v;
    }
    __syncthreads();
    for (int col = 0; col < SD; col++) {
        if (t < 96) prow[t] = aug[col][t];
        if (t < SD) fvec[t] = aug[t][col];
        __syncthreads();
        float ipv = 1.f / prow[col];
        for (int f = t; f < SD*96; f += 256) {
            int r = f / 96, c = f % 96;
            if (r == col) aug[r][c] = prow[c] * ipv;
            else          aug[r][c] = fmaf(-fvec[r]*ipv, prow[c], aug[r][c]);
        }
        __syncthreads();
    }
    if (t < SD*SD) { int r = t >> 4, c = t & 15; float v = aug[r][16+c]; g_Ad[t] = v; g_Apow[t] = v; }
    for (int f = t; f < SD*IDIM; f += 256) { int r = f / IDIM, c = f % IDIM; g_Bd[f] = aug[r][32+c]; }
    __syncthreads();
    for (int m = 1; m <= LCH/2; m <<= 1) {
        for (int f = t; f < m*256; f += 256) {
            int i = f >> 8, e = f & 255, r = e >> 4, c2 = e & 15;
            const float* L = g_Apow + i*256 + r*16;
            const float* R = g_Apow + (m-1)*256;
            float s = 0.f;
#pragma unroll
            for (int k = 0; k < 16; k++) s = fmaf(L[k], R[k*16 + c2], s);
            g_Apow[(m+i)*256 + e] = s;
        }
        __syncthreads();
    }
    if (t < 256) {
        int r = t >> 4, c = t & 15;
        g_ALpow[t] = (r == c) ? 1.f : 0.f;
        g_ALpow[256 + t] = g_Apow[(LCH-1)*256 + t];
    }
    __syncthreads();
    for (int m = 1; m <= 8; m <<= 1) {
        for (int f = t; f < m*256; f += 256) {
            int i = (f >> 8) + 1, e = f & 255, r = e >> 4, c2 = e & 15;
            const float* L = g_ALpow + i*256 + r*16;
            const float* R = g_ALpow + m*256;
            float s = 0.f;
#pragma unroll
            for (int k = 0; k < 16; k++) s = fmaf(L[k], R[k*16 + c2], s);
            g_ALpow[(m+i)*256 + e] = s;
        }
        __syncthreads();
    }
}

// ---------------- kBxS: u = x @ Bd^T + in-smem local scan ----------------
#define XSTR 66
#define USTR 20
__global__ void __launch_bounds__(256) kbxs(const float* __restrict__ x) {
    __shared__ __align__(16) float Xs[128*XSTR];
    __shared__ float Bs[16*66];
    __shared__ float As[16*17];
    int tid = threadIdx.x;
    size_t row0 = (size_t)blockIdx.x * 128;

    for (int i = tid; i < SD*IDIM; i += 256) {
        int nn = i >> 6, kk = i & 63;
        Bs[nn*66 + kk] = g_Bd[i];
    }
    if (tid < SD*SD) As[(tid >> 4)*17 + (tid & 15)] = g_Ad[tid];
#pragma unroll
    for (int i = 0; i < 16; i++) {
        int f = tid + 256*i;
        int r = f >> 5, qq = f & 31;
        float2 v = *(const float2*)(x + (row0 + r)*64 + qq*2);
        *(float2*)&Xs[r*XSTR + qq*2] = v;
    }
    __syncthreads();

    unsigned long long acc[4][4];
    int tr = tid >> 2, tc = tid & 3;
    if (tid < 128) {
#pragma unroll
        for (int m = 0; m < 4; m++)
#pragma unroll
            for (int c = 0; c < 4; c++) acc[m][c] = 0ull;
        const float* xa = Xs + tr*XSTR;            // rows tr + 32m (conflict-free banks)
#pragma unroll
        for (int kp = 0; kp < 32; kp++) {
            unsigned long long a2[4], b2[4];
#pragma unroll
            for (int m = 0; m < 4; m++)
                a2[m] = *(const unsigned long long*)(xa + (m*32)*XSTR + 2*kp);
#pragma unroll
            for (int c = 0; c < 4; c++)
                b2[c] = *(const unsigned long long*)(Bs + (tc + 4*c)*66 + 2*kp);
#pragma unroll
            for (int m = 0; m < 4; m++)
#pragma unroll
                for (int c = 0; c < 4; c++)
                    asm("fma.rn.f32x2 %0, %1, %2, %0;"
                        : "+l"(acc[m][c]) : "l"(a2[m]), "l"(b2[c]));
        }
    }
    __syncthreads();
    float* Us = Xs;
    if (tid < 128) {
#pragma unroll
        for (int m = 0; m < 4; m++)
#pragma unroll
            for (int c = 0; c < 4; c++) {
                float lo, hi;
                asm("mov.b64 {%0,%1}, %2;" : "=f"(lo), "=f"(hi) : "l"(acc[m][c]));
                Us[(tr + 32*m)*USTR + tc + 4*c] = lo + hi;
            }
    }
    __syncthreads();

    if (tid < 64) {
        int hw = tid >> 4, n = tid & 15;
        float Ar[16];
#pragma unroll
        for (int k = 0; k < 16; k++) Ar[k] = As[n*17 + k];
        float* u = Us + hw*32*USTR + n;
        float h = 0.f;
        float uc = u[0];
#pragma unroll
        for (int i = 0; i < LCH; i++) {
            float un = (i < LCH-1) ? u[(i+1)*USTR] : 0.f;
            float acc0 = uc, acc1 = 0.f, acc2 = 0.f, acc3 = 0.f;
#pragma unroll
            for (int m = 0; m < 16; m += 4) {
                acc0 = fmaf(Ar[m],   __shfl_sync(FULLMASK, h, m,   16), acc0);
                acc1 = fmaf(Ar[m+1], __shfl_sync(FULLMASK, h, m+1, 16), acc1);
                acc2 = fmaf(Ar[m+2], __shfl_sync(FULLMASK, h, m+2, 16), acc2);
                acc3 = fmaf(Ar[m+3], __shfl_sync(FULLMASK, h, m+3, 16), acc3);
            }
            h = (acc0 + acc1) + (acc2 + acc3);
            u[i*USTR] = h;
            uc = un;
        }
    }
    __syncthreads();

#pragma unroll
    for (int i = 0; i < 2; i++) {
        int f = tid + 256*i;
        int r = f >> 2, qq = f & 3;
        float4 v = *(const float4*)&Us[r*USTR + qq*4];
        *(float4*)(g_H + row0*SD + (size_t)f*4) = v;
    }
}

// ---------------- k2ab: superchunk prefixes + cross-superchunk scan ----------------
__global__ void __launch_bounds__(256) k2ab() {
    int tid = threadIdx.x;
    int b = blockIdx.x;
    int n = tid & 15;
    {
        int g = b*NSC + (tid >> 4);
        float Ar[16];
#pragma unroll
        for (int k = 0; k < 16; k++) Ar[k] = g_ALpow[256 + n*16 + k];
        float Pv = 0.f;
#pragma unroll
        for (int j = 0; j < NSUP; j++) {
            g_Pfx[(g*17 + j)*16 + n] = Pv;
            int c = g*NSUP + j;
            float s = g_H[((size_t)c*LCH + (LCH-1))*SD + n];
            float acc0 = s, acc1 = 0.f, acc2 = 0.f, acc3 = 0.f;
#pragma unroll
            for (int m = 0; m < 16; m += 4) {
                acc0 = fmaf(Ar[m],   __shfl_sync(FULLMASK, Pv, m,   16), acc0);
                acc1 = fmaf(Ar[m+1], __shfl_sync(FULLMASK, Pv, m+1, 16), acc1);
                acc2 = fmaf(Ar[m+2], __shfl_sync(FULLMASK, Pv, m+2, 16), acc2);
                acc3 = fmaf(Ar[m+3], __shfl_sync(FULLMASK, Pv, m+3, 16), acc3);
            }
            Pv = (acc0 + acc1) + (acc2 + acc3);
        }
        g_Pfx[(g*17 + 16)*16 + n] = Pv;
    }
    __syncthreads();
    if (tid < 16) {
        float Ar[16];
#pragma unroll
        for (int k = 0; k < 16; k++) Ar[k] = g_ALpow[16*256 + n*16 + k];
        float H = 0.f;
#pragma unroll
        for (int s = 0; s < NSC; s++) {
            int g = b*NSC + s;
            g_Hsup[g*16 + n] = H;
            float P16 = g_Pfx[(g*17 + 16)*16 + n];
            float acc0 = P16, acc1 = 0.f, acc2 = 0.f, acc3 = 0.f;
#pragma unroll
            for (int m = 0; m < 16; m += 4) {
                acc0 = fmaf(Ar[m],   __shfl_sync(FULLMASK, H, m,   16), acc0);
                acc1 = fmaf(Ar[m+1], __shfl_sync(FULLMASK, H, m+1, 16), acc1);
                acc2 = fmaf(Ar[m+2], __shfl_sync(FULLMASK, H, m+2, 16), acc2);
                acc3 = fmaf(Ar[m+3], __shfl_sync(FULLMASK, H, m+3, 16), acc3);
            }
            H = (acc0 + acc1) + (acc2 + acc3);
        }
    }
}

// ---------------- K3j: 128 thr, 8x8 tile, col-packed f32x2, conflict-free a-loads ----------------
#define ZSTR 42
#define WKS  72
#define APAD2 17
__global__ void __launch_bounds__(128, 4) k3j(const float* __restrict__ x,
                                              const float* __restrict__ C,
                                              const float* __restrict__ D,
                                              float* __restrict__ y) {
    __shared__ float Zs[128*ZSTR];
    __shared__ float Wk[80*WKS];
    __shared__ float sA2[2*16*APAD2];
    __shared__ float hpv[4*16];
    int tid = threadIdx.x;
    size_t row0 = (size_t)blockIdx.x * 128;
    int wid = tid >> 5;
    int wrow = wid * 32;
    int lr = (tid >> 3) & 3, lc = tid & 7;

    // Wk fill
#pragma unroll
    for (int i = 0; i < 32; i++) {
        int f = tid + 128*i;
        int o = f >> 6, k = f & 63;
        Wk[k*WKS + o] = D[f];
    }
#pragma unroll
    for (int i = 0; i < 8; i++) {
        int f = tid + 128*i;
        int o = f >> 4, kk = f & 15;
        Wk[(64 + kk)*WKS + o] = C[f];
    }
#pragma unroll
    for (int i = 0; i < 4; i++) {
        int f = tid + 128*i;
        int jl = f >> 8, e = f & 255;
        sA2[jl*(16*APAD2) + (e >> 4)*APAD2 + (e & 15)] = g_Apow[f];
    }
    if (tid < 64) {
        int cl = tid >> 4, n = tid & 15;
        int cg = blockIdx.x*4 + cl;
        int gsup = cg >> 4, js = cg & 15;
        float s = g_Pfx[((size_t)gsup*17 + js)*16 + n];
        const float* alr = g_ALpow + js*256 + n*16;
        const float* hs = g_Hsup + gsup*16;
#pragma unroll
        for (int k = 0; k < 16; k++) s = fmaf(alr[k], hs[k], s);
        hpv[cl*16 + n] = s;
    }
#pragma unroll
    for (int i = 0; i < 20; i++) {
        int f = tid + 128*i;
        int r = f / 20, q = f % 20;
        float2 v = *(const float2*)(x + (row0 + r)*64 + 2*q);
        *(float2*)&Zs[r*ZSTR + 2*q] = v;
    }

    unsigned long long acc[8][4];
#pragma unroll
    for (int m = 0; m < 8; m++)
#pragma unroll
        for (int c = 0; c < 4; c++) acc[m][c] = 0ull;

    // rows = wrow + lr + 4*m : lr-spacing 42 mod 32 = 10 -> banks {0,10,20,30}, conflict-free
    const float* za0 = Zs + (wrow + lr)*ZSTR;
    __syncthreads();

    // ---- phase 1 compute: k 0..39 ----
#pragma unroll 4
    for (int k = 0; k < 40; k++) {
        const float* wr = Wk + k*WKS + 2*lc;
        unsigned long long b2[4];
        b2[0] = *(const unsigned long long*)(wr);
        b2[1] = *(const unsigned long long*)(wr + 16);
        b2[2] = *(const unsigned long long*)(wr + 32);
        b2[3] = *(const unsigned long long*)(wr + 48);
#pragma unroll
        for (int m = 0; m < 8; m++) {
            float a = za0[(4*m)*ZSTR + k];
            unsigned long long a2;
            asm("mov.b64 %0, {%1, %1};" : "=l"(a2) : "f"(a));
#pragma unroll
            for (int c = 0; c < 4; c++)
                asm("fma.rn.f32x2 %0, %1, %2, %0;"
                    : "+l"(acc[m][c]) : "l"(a2), "l"(b2[c]));
        }
    }
    __syncthreads();
    // ---- phase 2 staging ----
#pragma unroll
    for (int i = 0; i < 12; i++) {
        int f = tid + 128*i;
        int r = f / 12, q = f % 12;
        float2 v = *(const float2*)(x + (row0 + r)*64 + 40 + 2*q);
        *(float2*)&Zs[r*ZSTR + 2*q] = v;
    }
#pragma unroll
    for (int i = 0; i < 8; i++) {
        int f = tid + 128*i;
        int r = f >> 3, q = f & 7;
        float2 v = *(const float2*)(g_H + (row0 + r)*16 + 2*q);
        *(float2*)&Zs[r*ZSTR + 24 + 2*q] = v;
    }
    __syncthreads();
    // ---- correction chains: 8 half-warps, A^2 steps, 16 iterations ----
    {
        int hw = tid >> 4, cl = hw >> 1, mph = hw & 1, n = tid & 15;
        const float* Am = sA2 + mph*(16*APAD2) + n*APAD2;
        const float* hp = hpv + cl*16;
        float w = 0.f;
#pragma unroll
        for (int k = 0; k < 16; k++) w = fmaf(Am[k], hp[k], w);
        float A2r[16];
#pragma unroll
        for (int k = 0; k < 16; k++) A2r[k] = sA2[1*(16*APAD2) + n*APAD2 + k];
#pragma unroll
        for (int s = 0; s < 16; s++) {
            int j = mph + 2*s;
            Zs[(cl*32 + j)*ZSTR + 24 + n] += w;
            if (s < 15) {
                float a0 = 0.f, a1 = 0.f, a2 = 0.f, a3 = 0.f;
#pragma unroll
                for (int m = 0; m < 16; m += 4) {
                    a0 = fmaf(A2r[m],   __shfl_sync(FULLMASK, w, m,   16), a0);
                    a1 = fmaf(A2r[m+1], __shfl_sync(FULLMASK, w, m+1, 16), a1);
                    a2 = fmaf(A2r[m+2], __shfl_sync(FULLMASK, w, m+2, 16), a2);
                    a3 = fmaf(A2r[m+3], __shfl_sync(FULLMASK, w, m+3, 16), a3);
                }
                w = (a0 + a1) + (a2 + a3);
            }
        }
    }
    __syncthreads();
    // ---- phase 2 compute: k 40..79 ----
#pragma unroll 4
    for (int k = 0; k < 40; k++) {
        const float* wr = Wk + (40 + k)*WKS + 2*lc;
        unsigned long long b2[4];
        b2[0] = *(const unsigned long long*)(wr);
        b2[1] = *(const unsigned long long*)(wr + 16);
        b2[2] = *(const unsigned long long*)(wr + 32);
        b2[3] = *(const unsigned long long*)(wr + 48);
#pragma unroll
        for (int m = 0; m < 8; m++) {
            float a = za0[(4*m)*ZSTR + k];
            unsigned long long a2;
            asm("mov.b64 %0, {%1, %1};" : "=l"(a2) : "f"(a));
#pragma unroll
            for (int c = 0; c < 4; c++)
                asm("fma.rn.f32x2 %0, %1, %2, %0;"
                    : "+l"(acc[m][c]) : "l"(a2), "l"(b2[c]));
        }
    }

#pragma unroll
    for (int m = 0; m < 8; m++) {
        size_t row = row0 + wrow + lr + 4*m;
#pragma unroll
        for (int c = 0; c < 4; c++) {
            float lo, hi;
            asm("mov.b64 {%0,%1}, %2;" : "=f"(lo), "=f"(hi) : "l"(acc[m][c]));
            *(float2*)&y[row*64 + 2*lc + 16*c] = make_float2(lo, hi);
        }
    }
}

extern "C" void kernel_launch(void* const* d_in, const int* in_sizes, int n_in,
                              void* d_out, int out_size) {
    const float* x  = (const float*)d_in[0];
    const float* ll = (const float*)d_in[1];
    const float* p  = (const float*)d_in[2];
    const float* q  = (const float*)d_in[3];
    const float* B  = (const float*)d_in[4];
    const float* C  = (const float*)d_in[5];
    const float* D  = (const float*)d_in[6];
    const float* P  = (const float*)d_in[7];
    float* y = (float*)d_out;

    k0_setup<<<1, 256>>>(ll, p, q, B, P);
    kbxs<<<(NBATCH*SEQLEN)/128, 256>>>(x);
    k2ab<<<NBATCH, 256>>>();
    k3j<<<(NBATCH*SEQLEN)/128, 128>>>(x, C, D, y);   // profiled slot (4th)
}